// round 1
// baseline (speedup 1.0000x reference)
#include <cuda_runtime.h>
#include <cuda_bf16.h>

// ---------------------------------------------------------------------------
// SelfAttention: x(8,2048,512) -> qkv -> 4-head attention (dh=64) -> out proj
// Round-1 baseline: fp32 SIMT. 3 kernels:
//   1) SGEMM  x @ w_qkv              -> g_qkv  [16384 x 768]
//   2) flash-attention per (b,h)     -> g_attn [16384 x 256]
//   3) SGEMM  g_attn @ w_out + b_out -> out    [16384 x 512]
// ---------------------------------------------------------------------------

#define NTOK   (8 * 2048)
#define DMODEL 512
#define INNER  256
#define QKVN   768
#define HEADS  4
#define DH     64
#define TSEQ   2048

// Scratch (device globals: no runtime allocation allowed)
__device__ float g_qkv[NTOK * QKVN];    // 48 MB
__device__ float g_attn[NTOK * INNER];  // 16 MB

// ---------------------------------------------------------------------------
// Classic 128x128x8 SGEMM, 256 threads, 8x8 micro-tile in 2x2 quadrants
// C[M,N] = A[M,K] @ B[K,N] (+ bias[N] if bias != nullptr)
// Requires: M%128==0, N%128==0, K%8==0
// ---------------------------------------------------------------------------
__global__ __launch_bounds__(256, 2) void sgemm_kernel(
    const float* __restrict__ A, const float* __restrict__ B,
    const float* __restrict__ bias, float* __restrict__ C,
    int M, int N, int K)
{
    __shared__ float As[8][128];
    __shared__ float Bs[8][128];

    const int tid  = threadIdx.x;
    const int tx   = tid & 15;     // 0..15
    const int ty   = tid >> 4;     // 0..15
    const int row0 = blockIdx.y * 128;
    const int col0 = blockIdx.x * 128;

    // global load mapping
    const int aRow = tid >> 1;           // 0..127
    const int aCol = (tid & 1) * 4;      // 0 or 4
    const int bRow = tid >> 5;           // 0..7
    const int bCol = (tid & 31) * 4;     // 0..124

    const float* Aptr = A + (size_t)(row0 + aRow) * K + aCol;
    const float* Bptr = B + (size_t)bRow * N + col0 + bCol;

    float acc[8][8];
    #pragma unroll
    for (int i = 0; i < 8; i++)
        #pragma unroll
        for (int j = 0; j < 8; j++) acc[i][j] = 0.f;

    for (int k0 = 0; k0 < K; k0 += 8) {
        float4 av = *reinterpret_cast<const float4*>(Aptr + k0);
        float4 bv = *reinterpret_cast<const float4*>(Bptr + (size_t)k0 * N);
        As[aCol + 0][aRow] = av.x;
        As[aCol + 1][aRow] = av.y;
        As[aCol + 2][aRow] = av.z;
        As[aCol + 3][aRow] = av.w;
        *reinterpret_cast<float4*>(&Bs[bRow][bCol]) = bv;
        __syncthreads();

        #pragma unroll
        for (int kk = 0; kk < 8; kk++) {
            float a[8], b[8];
            float4 t;
            t = *reinterpret_cast<const float4*>(&As[kk][ty * 4]);
            a[0] = t.x; a[1] = t.y; a[2] = t.z; a[3] = t.w;
            t = *reinterpret_cast<const float4*>(&As[kk][64 + ty * 4]);
            a[4] = t.x; a[5] = t.y; a[6] = t.z; a[7] = t.w;
            t = *reinterpret_cast<const float4*>(&Bs[kk][tx * 4]);
            b[0] = t.x; b[1] = t.y; b[2] = t.z; b[3] = t.w;
            t = *reinterpret_cast<const float4*>(&Bs[kk][64 + tx * 4]);
            b[4] = t.x; b[5] = t.y; b[6] = t.z; b[7] = t.w;
            #pragma unroll
            for (int i = 0; i < 8; i++)
                #pragma unroll
                for (int j = 0; j < 8; j++)
                    acc[i][j] += a[i] * b[j];
        }
        __syncthreads();
    }

    // bias (per output column)
    float4 bia0 = make_float4(0.f, 0.f, 0.f, 0.f), bia1 = bia0;
    if (bias) {
        bia0 = *reinterpret_cast<const float4*>(&bias[col0 + tx * 4]);
        bia1 = *reinterpret_cast<const float4*>(&bias[col0 + 64 + tx * 4]);
    }

    #pragma unroll
    for (int i = 0; i < 8; i++) {
        int r = row0 + ((i < 4) ? (ty * 4 + i) : (64 + ty * 4 + i - 4));
        float4 v0 = make_float4(acc[i][0] + bia0.x, acc[i][1] + bia0.y,
                                acc[i][2] + bia0.z, acc[i][3] + bia0.w);
        float4 v1 = make_float4(acc[i][4] + bia1.x, acc[i][5] + bia1.y,
                                acc[i][6] + bia1.z, acc[i][7] + bia1.w);
        *reinterpret_cast<float4*>(&C[(size_t)r * N + col0 + tx * 4])      = v0;
        *reinterpret_cast<float4*>(&C[(size_t)r * N + col0 + 64 + tx * 4]) = v1;
    }
}

// ---------------------------------------------------------------------------
// Flash attention, fp32. One block per (q-tile of 64, head, batch).
// 256 threads; each thread owns a 4x4 (row x dh-col) tile of S and O.
// Dynamic smem: Q/K/V/S tiles (64x65 each) + m/l/alpha rows.
// ---------------------------------------------------------------------------
#define BQ    64
#define BKV   64
#define PITCH 65
#define FA_SMEM_FLOATS (4 * BQ * PITCH + 3 * BQ)
#define FA_SMEM_BYTES  (FA_SMEM_FLOATS * 4)

__global__ __launch_bounds__(256) void flash_attn_kernel(
    const float* __restrict__ qkv, float* __restrict__ attn_out)
{
    extern __shared__ float sm[];
    float* Qs = sm;                      // BQ * PITCH (pre-scaled by 1/8)
    float* Ks = Qs + BQ * PITCH;
    float* Vs = Ks + BKV * PITCH;
    float* Ss = Vs + BKV * PITCH;
    float* m_s = Ss + BQ * PITCH;       // BQ
    float* l_s = m_s + BQ;              // BQ
    float* al_s = l_s + BQ;             // BQ

    const int tid = threadIdx.x;
    const int tx  = tid & 15;
    const int ty  = tid >> 4;
    const int qt  = blockIdx.x;   // 0..31
    const int h   = blockIdx.y;   // 0..3
    const int bb  = blockIdx.z;   // 0..7

    const int tok_q0 = bb * TSEQ + qt * BQ;
    const int q_off = h * DH;
    const int k_off = INNER + h * DH;
    const int v_off = 2 * INNER + h * DH;

    // load Q tile, pre-scaled by dh^-0.5 = 0.125
    for (int i = tid; i < BQ * DH; i += 256) {
        int r = i >> 6, c = i & 63;
        Qs[r * PITCH + c] = qkv[(size_t)(tok_q0 + r) * QKVN + q_off + c] * 0.125f;
    }
    if (tid < BQ) { m_s[tid] = -1e30f; l_s[tid] = 0.f; }

    float o[4][4];
    #pragma unroll
    for (int i = 0; i < 4; i++)
        #pragma unroll
        for (int j = 0; j < 4; j++) o[i][j] = 0.f;

    for (int kt = 0; kt < TSEQ / BKV; kt++) {
        const int tok_k0 = bb * TSEQ + kt * BKV;
        for (int i = tid; i < BKV * DH; i += 256) {
            int r = i >> 6, c = i & 63;
            size_t base = (size_t)(tok_k0 + r) * QKVN;
            Ks[r * PITCH + c] = qkv[base + k_off + c];
            Vs[r * PITCH + c] = qkv[base + v_off + c];
        }
        __syncthreads();

        // S = Q @ K^T (thread: rows ty*4.., cols tx*4..)
        float s[4][4];
        #pragma unroll
        for (int i = 0; i < 4; i++)
            #pragma unroll
            for (int j = 0; j < 4; j++) s[i][j] = 0.f;
        #pragma unroll 8
        for (int c = 0; c < DH; c++) {
            float qv[4], kv[4];
            #pragma unroll
            for (int i = 0; i < 4; i++) qv[i] = Qs[(ty * 4 + i) * PITCH + c];
            #pragma unroll
            for (int j = 0; j < 4; j++) kv[j] = Ks[(tx * 4 + j) * PITCH + c];
            #pragma unroll
            for (int i = 0; i < 4; i++)
                #pragma unroll
                for (int j = 0; j < 4; j++)
                    s[i][j] += qv[i] * kv[j];
        }
        #pragma unroll
        for (int i = 0; i < 4; i++)
            #pragma unroll
            for (int j = 0; j < 4; j++)
                Ss[(ty * 4 + i) * PITCH + tx * 4 + j] = s[i][j];
        __syncthreads();

        // online softmax: 4 threads per row (r = tid/4)
        {
            const int r  = tid >> 2;
            const int qd = tid & 3;
            float* srow = &Ss[r * PITCH];
            float mx = -1e30f;
            #pragma unroll
            for (int j = 0; j < 16; j++) mx = fmaxf(mx, srow[qd * 16 + j]);
            mx = fmaxf(mx, __shfl_xor_sync(0xffffffffu, mx, 1));
            mx = fmaxf(mx, __shfl_xor_sync(0xffffffffu, mx, 2));
            float m_old = m_s[r];
            float m_new = fmaxf(m_old, mx);
            float sum = 0.f;
            #pragma unroll
            for (int j = 0; j < 16; j++) {
                float p = __expf(srow[qd * 16 + j] - m_new);
                srow[qd * 16 + j] = p;
                sum += p;
            }
            sum += __shfl_xor_sync(0xffffffffu, sum, 1);
            sum += __shfl_xor_sync(0xffffffffu, sum, 2);
            if (qd == 0) {
                float alpha = __expf(m_old - m_new);
                l_s[r] = l_s[r] * alpha + sum;
                m_s[r] = m_new;
                al_s[r] = alpha;
            }
        }
        __syncthreads();

        // rescale O, then O += P @ V
        float al[4];
        #pragma unroll
        for (int i = 0; i < 4; i++) al[i] = al_s[ty * 4 + i];
        #pragma unroll
        for (int i = 0; i < 4; i++)
            #pragma unroll
            for (int j = 0; j < 4; j++) o[i][j] *= al[i];

        #pragma unroll 8
        for (int j = 0; j < BKV; j++) {
            float pv[4], vv[4];
            #pragma unroll
            for (int i = 0; i < 4; i++) pv[i] = Ss[(ty * 4 + i) * PITCH + j];
            #pragma unroll
            for (int jj = 0; jj < 4; jj++) vv[jj] = Vs[j * PITCH + tx * 4 + jj];
            #pragma unroll
            for (int i = 0; i < 4; i++)
                #pragma unroll
                for (int jj = 0; jj < 4; jj++)
                    o[i][jj] += pv[i] * vv[jj];
        }
        __syncthreads();
    }

    // normalize + write (b, t, h*dh + c)
    float linv[4];
    #pragma unroll
    for (int i = 0; i < 4; i++) linv[i] = 1.f / l_s[ty * 4 + i];
    #pragma unroll
    for (int i = 0; i < 4; i++) {
        int tok = tok_q0 + ty * 4 + i;
        #pragma unroll
        for (int j = 0; j < 4; j++) {
            int c = tx * 4 + j;
            attn_out[(size_t)tok * INNER + h * DH + c] = o[i][j] * linv[i];
        }
    }
}

// ---------------------------------------------------------------------------
extern "C" void kernel_launch(void* const* d_in, const int* in_sizes, int n_in,
                              void* d_out, int out_size)
{
    (void)in_sizes; (void)n_in; (void)out_size;
    const float* x     = (const float*)d_in[0];
    const float* w_qkv = (const float*)d_in[1];
    const float* w_out = (const float*)d_in[2];
    const float* b_out = (const float*)d_in[3];
    float* out = (float*)d_out;

    float* qkv_ptr = nullptr;
    float* attn_ptr = nullptr;
    cudaGetSymbolAddress((void**)&qkv_ptr, g_qkv);
    cudaGetSymbolAddress((void**)&attn_ptr, g_attn);

    // 1) QKV projection: [16384,512] @ [512,768]
    {
        dim3 grid(QKVN / 128, NTOK / 128);
        sgemm_kernel<<<grid, 256>>>(x, w_qkv, nullptr, qkv_ptr, NTOK, QKVN, DMODEL);
    }

    // 2) attention
    {
        cudaFuncSetAttribute(flash_attn_kernel,
                             cudaFuncAttributeMaxDynamicSharedMemorySize,
                             FA_SMEM_BYTES);
        dim3 grid(TSEQ / BQ, HEADS, 8);
        flash_attn_kernel<<<grid, 256, FA_SMEM_BYTES>>>(qkv_ptr, attn_ptr);
    }

    // 3) output projection: [16384,256] @ [256,512] + bias
    {
        dim3 grid(DMODEL / 128, NTOK / 128);
        sgemm_kernel<<<grid, 256>>>(attn_ptr, w_out, b_out, out, NTOK, DMODEL, INNER);
    }
}

// round 3
// speedup vs baseline: 1.8168x; 1.8168x over previous
#include <cuda_runtime.h>
#include <cstdint>

// ===========================================================================
// SelfAttention via mma.sync tf32 (HMMA) — compute_103-safe tensor path.
//   K1: mma_gemm   x @ w_qkv            -> g_qkv  [16384 x 768]
//   K2: mma_flash  attention            -> g_attn [16384 x 256]
//   K1: mma_gemm   g_attn @ w_out + b   -> out    [16384 x 512]
// ===========================================================================

#define NTOK   16384
#define DMODEL 512
#define INNER  256
#define QKVN   768
#define HEADS  4
#define DH     64
#define TSEQ   2048

__device__ float g_qkv[NTOK * QKVN];    // 48 MB
__device__ float g_attn[NTOK * INNER];  // 16 MB

__device__ __forceinline__ uint32_t f2tf32(float x) {
    uint32_t r;
    asm("cvt.rna.tf32.f32 %0, %1;" : "=r"(r) : "f"(x));
    return r;
}

// D = A(16x8) @ B(8x8) + D, tf32 inputs, f32 accum
__device__ __forceinline__ void mma_tf32(float* c, const uint32_t* a,
                                         uint32_t b0, uint32_t b1) {
    asm volatile(
        "mma.sync.aligned.m16n8k8.row.col.f32.tf32.tf32.f32 "
        "{%0,%1,%2,%3}, {%4,%5,%6,%7}, {%8,%9}, {%0,%1,%2,%3};"
        : "+f"(c[0]), "+f"(c[1]), "+f"(c[2]), "+f"(c[3])
        : "r"(a[0]), "r"(a[1]), "r"(a[2]), "r"(a[3]), "r"(b0), "r"(b1));
}

// ---------------------------------------------------------------------------
// GEMM: C[M,N] = A[M,K] @ B[K,N] (+bias). 256 thr, tile 128x128, kchunk 32.
// Warp grid 4(m) x 2(n); warp tile 32x64 = 2 mtiles x 8 ntiles of m16n8k8.
// As pitch 36 (bank 4g+tg), Bs pitch 132 (bank 4tg+g): conflict-free frags.
// ---------------------------------------------------------------------------
#define AP 36
#define BP 132

__global__ __launch_bounds__(256) void mma_gemm_kernel(
    const float* __restrict__ A, const float* __restrict__ B,
    const float* __restrict__ bias, float* __restrict__ C,
    int M, int N, int K)
{
    __shared__ uint32_t As[128 * AP];
    __shared__ uint32_t Bs[32 * BP];

    const int tid = threadIdx.x;
    const int wid = tid >> 5, lane = tid & 31;
    const int g = lane >> 2, tg = lane & 3;
    const int wm = wid & 3, wn = wid >> 2;
    const int row0 = blockIdx.y * 128, col0 = blockIdx.x * 128;

    float c[2][8][4];
    #pragma unroll
    for (int mt = 0; mt < 2; mt++)
        #pragma unroll
        for (int nt = 0; nt < 8; nt++)
            #pragma unroll
            for (int j = 0; j < 4; j++) c[mt][nt][j] = 0.f;

    for (int k0 = 0; k0 < K; k0 += 32) {
        #pragma unroll
        for (int i = 0; i < 4; i++) {                      // A tile 128x32
            int flat = tid * 4 + i * 1024;
            int r = flat >> 5, cc = flat & 31;
            float4 v = *reinterpret_cast<const float4*>(
                A + (size_t)(row0 + r) * K + k0 + cc);
            As[r * AP + cc + 0] = f2tf32(v.x);
            As[r * AP + cc + 1] = f2tf32(v.y);
            As[r * AP + cc + 2] = f2tf32(v.z);
            As[r * AP + cc + 3] = f2tf32(v.w);
        }
        #pragma unroll
        for (int i = 0; i < 4; i++) {                      // B tile 32x128
            int flat = tid * 4 + i * 1024;
            int r = flat >> 7, cc = flat & 127;
            float4 v = *reinterpret_cast<const float4*>(
                B + (size_t)(k0 + r) * N + col0 + cc);
            Bs[r * BP + cc + 0] = f2tf32(v.x);
            Bs[r * BP + cc + 1] = f2tf32(v.y);
            Bs[r * BP + cc + 2] = f2tf32(v.z);
            Bs[r * BP + cc + 3] = f2tf32(v.w);
        }
        __syncthreads();

        #pragma unroll
        for (int ks = 0; ks < 4; ks++) {
            uint32_t a[2][4], b[8][2];
            #pragma unroll
            for (int mt = 0; mt < 2; mt++) {
                int base = (wm * 32 + mt * 16) * AP + ks * 8;
                a[mt][0] = As[base + g * AP + tg];
                a[mt][1] = As[base + (g + 8) * AP + tg];
                a[mt][2] = As[base + g * AP + tg + 4];
                a[mt][3] = As[base + (g + 8) * AP + tg + 4];
            }
            #pragma unroll
            for (int nt = 0; nt < 8; nt++) {
                int bb = (ks * 8 + tg) * BP + wn * 64 + nt * 8 + g;
                b[nt][0] = Bs[bb];
                b[nt][1] = Bs[bb + 4 * BP];
            }
            #pragma unroll
            for (int mt = 0; mt < 2; mt++)
                #pragma unroll
                for (int nt = 0; nt < 8; nt++)
                    mma_tf32(c[mt][nt], a[mt], b[nt][0], b[nt][1]);
        }
        __syncthreads();
    }

    #pragma unroll
    for (int mt = 0; mt < 2; mt++) {
        int r = row0 + wm * 32 + mt * 16 + g;
        #pragma unroll
        for (int nt = 0; nt < 8; nt++) {
            int cc = col0 + wn * 64 + nt * 8 + 2 * tg;
            float bx = 0.f, by = 0.f;
            if (bias) { bx = bias[cc]; by = bias[cc + 1]; }
            float2 v0 = make_float2(c[mt][nt][0] + bx, c[mt][nt][1] + by);
            float2 v1 = make_float2(c[mt][nt][2] + bx, c[mt][nt][3] + by);
            *reinterpret_cast<float2*>(C + (size_t)r * N + cc) = v0;
            *reinterpret_cast<float2*>(C + (size_t)(r + 8) * N + cc) = v1;
        }
    }
}

// ---------------------------------------------------------------------------
// Flash attention, mma.sync tf32. 256 thr / 8 warps per CTA.
// CTA: 128 q-rows of one (batch, head). kv tiles of 128. dh = 64.
// Warp w owns q-rows [16w, 16w+16); m/l/O register-resident.
// Qs/Ks/Vs pitch 68 (frag banks 4g+tg / 4tg+g), Ps pitch 132.
// ---------------------------------------------------------------------------
#define QP 68
#define PP 132
#define FA_QS   0
#define FA_KS   (128 * QP)
#define FA_VS   (2 * 128 * QP)
#define FA_PS   (3 * 128 * QP)
#define FA_WORDS (3 * 128 * QP + 128 * PP)
#define FA_BYTES (FA_WORDS * 4)          // 172032

__global__ __launch_bounds__(256) void mma_flash_kernel(
    const float* __restrict__ qkv, float* __restrict__ attn)
{
    extern __shared__ uint32_t sm[];
    uint32_t* Qs = sm + FA_QS;
    uint32_t* Ks = sm + FA_KS;
    uint32_t* Vs = sm + FA_VS;
    uint32_t* Ps = sm + FA_PS;

    const int tid = threadIdx.x;
    const int wid = tid >> 5, lane = tid & 31;
    const int g = lane >> 2, tg = lane & 3;
    const int qt = blockIdx.x, h = blockIdx.y, bb = blockIdx.z;
    const int tok_q0 = bb * TSEQ + qt * 128;

    // Q tile (pre-scaled by dh^-0.5 = 0.125)
    #pragma unroll
    for (int i = 0; i < 8; i++) {
        int flat = tid * 4 + i * 1024;
        int r = flat >> 6, cc = flat & 63;
        float4 v = *reinterpret_cast<const float4*>(
            qkv + (size_t)(tok_q0 + r) * QKVN + h * DH + cc);
        Qs[r * QP + cc + 0] = f2tf32(v.x * 0.125f);
        Qs[r * QP + cc + 1] = f2tf32(v.y * 0.125f);
        Qs[r * QP + cc + 2] = f2tf32(v.z * 0.125f);
        Qs[r * QP + cc + 3] = f2tf32(v.w * 0.125f);
    }

    float m0 = -1e30f, m1 = -1e30f, l0 = 0.f, l1 = 0.f;
    float o[8][4];
    #pragma unroll
    for (int nt = 0; nt < 8; nt++)
        #pragma unroll
        for (int j = 0; j < 4; j++) o[nt][j] = 0.f;

    for (int kt = 0; kt < TSEQ / 128; kt++) {
        const int tok_k0 = bb * TSEQ + kt * 128;
        __syncthreads();   // prior iter done reading Ks/Vs
        #pragma unroll
        for (int i = 0; i < 8; i++) {
            int flat = tid * 4 + i * 1024;
            int r = flat >> 6, cc = flat & 63;
            size_t base = (size_t)(tok_k0 + r) * QKVN + h * DH + cc;
            float4 kv4 = *reinterpret_cast<const float4*>(qkv + base + INNER);
            float4 vv4 = *reinterpret_cast<const float4*>(qkv + base + 2 * INNER);
            Ks[r * QP + cc + 0] = f2tf32(kv4.x);
            Ks[r * QP + cc + 1] = f2tf32(kv4.y);
            Ks[r * QP + cc + 2] = f2tf32(kv4.z);
            Ks[r * QP + cc + 3] = f2tf32(kv4.w);
            Vs[r * QP + cc + 0] = f2tf32(vv4.x);
            Vs[r * QP + cc + 1] = f2tf32(vv4.y);
            Vs[r * QP + cc + 2] = f2tf32(vv4.z);
            Vs[r * QP + cc + 3] = f2tf32(vv4.w);
        }
        __syncthreads();

        // ---- S = Q @ K^T : warp tile 16 x 128 (16 ntiles), K = 64 (8 ks)
        float s[16][4];
        #pragma unroll
        for (int nt = 0; nt < 16; nt++)
            #pragma unroll
            for (int j = 0; j < 4; j++) s[nt][j] = 0.f;
        #pragma unroll
        for (int ks = 0; ks < 8; ks++) {
            uint32_t a[4];
            int base = (wid * 16) * QP + ks * 8;
            a[0] = Qs[base + g * QP + tg];
            a[1] = Qs[base + (g + 8) * QP + tg];
            a[2] = Qs[base + g * QP + tg + 4];
            a[3] = Qs[base + (g + 8) * QP + tg + 4];
            #pragma unroll
            for (int nt = 0; nt < 16; nt++) {
                int bidx = (nt * 8 + g) * QP + ks * 8 + tg;
                mma_tf32(s[nt], a, Ks[bidx], Ks[bidx + 4]);
            }
        }

        // ---- online softmax (rows wid*16+g and wid*16+g+8)
        float mx0 = -1e30f, mx1 = -1e30f;
        #pragma unroll
        for (int nt = 0; nt < 16; nt++) {
            mx0 = fmaxf(mx0, fmaxf(s[nt][0], s[nt][1]));
            mx1 = fmaxf(mx1, fmaxf(s[nt][2], s[nt][3]));
        }
        mx0 = fmaxf(mx0, __shfl_xor_sync(0xffffffffu, mx0, 1));
        mx0 = fmaxf(mx0, __shfl_xor_sync(0xffffffffu, mx0, 2));
        mx1 = fmaxf(mx1, __shfl_xor_sync(0xffffffffu, mx1, 1));
        mx1 = fmaxf(mx1, __shfl_xor_sync(0xffffffffu, mx1, 2));
        const float mn0 = fmaxf(m0, mx0), mn1 = fmaxf(m1, mx1);
        const float al0 = __expf(m0 - mn0), al1 = __expf(m1 - mn1);
        float sum0 = 0.f, sum1 = 0.f;
        #pragma unroll
        for (int nt = 0; nt < 16; nt++) {
            s[nt][0] = __expf(s[nt][0] - mn0);
            s[nt][1] = __expf(s[nt][1] - mn0);
            s[nt][2] = __expf(s[nt][2] - mn1);
            s[nt][3] = __expf(s[nt][3] - mn1);
            sum0 += s[nt][0] + s[nt][1];
            sum1 += s[nt][2] + s[nt][3];
        }
        sum0 += __shfl_xor_sync(0xffffffffu, sum0, 1);
        sum0 += __shfl_xor_sync(0xffffffffu, sum0, 2);
        sum1 += __shfl_xor_sync(0xffffffffu, sum1, 1);
        sum1 += __shfl_xor_sync(0xffffffffu, sum1, 2);
        l0 = l0 * al0 + sum0; m0 = mn0;
        l1 = l1 * al1 + sum1; m1 = mn1;
        #pragma unroll
        for (int nt = 0; nt < 8; nt++) {
            o[nt][0] *= al0; o[nt][1] *= al0;
            o[nt][2] *= al1; o[nt][3] *= al1;
        }
        // P -> SMEM (per-warp rows only; no cross-warp hazard)
        {
            int r0 = (wid * 16 + g) * PP, r1 = (wid * 16 + g + 8) * PP;
            #pragma unroll
            for (int nt = 0; nt < 16; nt++) {
                int cc = nt * 8 + 2 * tg;
                Ps[r0 + cc]     = f2tf32(s[nt][0]);
                Ps[r0 + cc + 1] = f2tf32(s[nt][1]);
                Ps[r1 + cc]     = f2tf32(s[nt][2]);
                Ps[r1 + cc + 1] = f2tf32(s[nt][3]);
            }
        }
        __syncwarp();

        // ---- O += P @ V : warp tile 16 x 64 (8 ntiles), K = 128 (16 ks)
        #pragma unroll
        for (int ks = 0; ks < 16; ks++) {
            uint32_t a[4];
            int base = (wid * 16) * PP + ks * 8;
            a[0] = Ps[base + g * PP + tg];
            a[1] = Ps[base + (g + 8) * PP + tg];
            a[2] = Ps[base + g * PP + tg + 4];
            a[3] = Ps[base + (g + 8) * PP + tg + 4];
            #pragma unroll
            for (int nt = 0; nt < 8; nt++) {
                int bidx = (ks * 8 + tg) * QP + nt * 8 + g;
                mma_tf32(o[nt], a, Vs[bidx], Vs[bidx + 4 * QP]);
            }
        }
    }

    const float li0 = 1.f / l0, li1 = 1.f / l1;
    const int r = tok_q0 + wid * 16 + g;
    #pragma unroll
    for (int nt = 0; nt < 8; nt++) {
        int cc = h * DH + nt * 8 + 2 * tg;
        float2 v0 = make_float2(o[nt][0] * li0, o[nt][1] * li0);
        float2 v1 = make_float2(o[nt][2] * li1, o[nt][3] * li1);
        *reinterpret_cast<float2*>(attn + (size_t)r * INNER + cc) = v0;
        *reinterpret_cast<float2*>(attn + (size_t)(r + 8) * INNER + cc) = v1;
    }
}

// ---------------------------------------------------------------------------
extern "C" void kernel_launch(void* const* d_in, const int* in_sizes, int n_in,
                              void* d_out, int out_size)
{
    (void)in_sizes; (void)n_in; (void)out_size;
    const float* x     = (const float*)d_in[0];
    const float* w_qkv = (const float*)d_in[1];
    const float* w_out = (const float*)d_in[2];
    const float* b_out = (const float*)d_in[3];
    float* out = (float*)d_out;

    float *qkv_p, *attn_p;
    cudaGetSymbolAddress((void**)&qkv_p,  g_qkv);
    cudaGetSymbolAddress((void**)&attn_p, g_attn);

    cudaFuncSetAttribute(mma_flash_kernel,
        cudaFuncAttributeMaxDynamicSharedMemorySize, FA_BYTES);

    // QKV projection: [16384,512] @ [512,768]
    mma_gemm_kernel<<<dim3(QKVN / 128, NTOK / 128), 256>>>(
        x, w_qkv, nullptr, qkv_p, NTOK, QKVN, DMODEL);
    // attention
    mma_flash_kernel<<<dim3(TSEQ / 128, HEADS, 8), 256, FA_BYTES>>>(
        qkv_p, attn_p);
    // output projection: [16384,256] @ [256,512] + bias
    mma_gemm_kernel<<<dim3(DMODEL / 128, NTOK / 128), 256>>>(
        attn_p, w_out, b_out, out, NTOK, DMODEL, INNER);
}

// round 4
// speedup vs baseline: 3.0087x; 1.6561x over previous
#include <cuda_runtime.h>
#include <cstdint>

// ===========================================================================
// SelfAttention via mma.sync tf32 — Round 4: bigger warp M-tiles for B-frag
// reuse (crossbar-bound fix) + register-prefetch pipelined GEMM.
//   K1: mma_gemm   x @ w_qkv            -> g_qkv  [16384 x 768]
//   K2: mma_flash  attention            -> g_attn [16384 x 256]
//   K1: mma_gemm   g_attn @ w_out + b   -> out    [16384 x 512]
// ===========================================================================

#define NTOK   16384
#define DMODEL 512
#define INNER  256
#define QKVN   768
#define HEADS  4
#define DH     64
#define TSEQ   2048

__device__ float g_qkv[NTOK * QKVN];    // 48 MB
__device__ float g_attn[NTOK * INNER];  // 16 MB

__device__ __forceinline__ uint32_t f2tf32(float x) {
    uint32_t r;
    asm("cvt.rna.tf32.f32 %0, %1;" : "=r"(r) : "f"(x));
    return r;
}

// D = A(16x8) @ B(8x8) + D, tf32 inputs, f32 accum
__device__ __forceinline__ void mma_tf32(float* c, const uint32_t* a,
                                         uint32_t b0, uint32_t b1) {
    asm volatile(
        "mma.sync.aligned.m16n8k8.row.col.f32.tf32.tf32.f32 "
        "{%0,%1,%2,%3}, {%4,%5,%6,%7}, {%8,%9}, {%0,%1,%2,%3};"
        : "+f"(c[0]), "+f"(c[1]), "+f"(c[2]), "+f"(c[3])
        : "r"(a[0]), "r"(a[1]), "r"(a[2]), "r"(a[3]), "r"(b0), "r"(b1));
}

// ---------------------------------------------------------------------------
// GEMM: C[M,N] = A[M,K] @ B[K,N] (+bias). 256 thr, CTA tile 256x128,
// kchunk 32, warp grid 4(m) x 2(n), warp tile 64x64 (4 mtiles x 8 ntiles).
// Register-prefetch pipeline on global loads.
// ---------------------------------------------------------------------------
#define AP 36
#define BP 132
#define GM_BS    (256 * AP)              // word offset of Bs
#define GM_WORDS (GM_BS + 32 * BP)
#define GM_BYTES (GM_WORDS * 4)          // 53760 B

__global__ __launch_bounds__(256, 1) void mma_gemm_kernel(
    const float* __restrict__ A, const float* __restrict__ B,
    const float* __restrict__ bias, float* __restrict__ C,
    int M, int N, int K)
{
    extern __shared__ uint32_t sm[];
    uint32_t* As = sm;            // 256 x AP
    uint32_t* Bs = sm + GM_BS;    // 32 x BP

    const int tid = threadIdx.x;
    const int wid = tid >> 5, lane = tid & 31;
    const int g = lane >> 2, tg = lane & 3;
    const int wm = wid & 3, wn = wid >> 2;
    const int row0 = blockIdx.y * 256, col0 = blockIdx.x * 128;

    float c[4][8][4];
    #pragma unroll
    for (int mt = 0; mt < 4; mt++)
        #pragma unroll
        for (int nt = 0; nt < 8; nt++)
            #pragma unroll
            for (int j = 0; j < 4; j++) c[mt][nt][j] = 0.f;

    const int nchunks = K >> 5;
    float4 av[8], bv[4];

    // prefetch chunk 0
    #pragma unroll
    for (int i = 0; i < 8; i++) {
        int flat = tid * 4 + i * 1024;
        int r = flat >> 5, cc = flat & 31;
        av[i] = *reinterpret_cast<const float4*>(A + (size_t)(row0 + r) * K + cc);
    }
    #pragma unroll
    for (int i = 0; i < 4; i++) {
        int flat = tid * 4 + i * 1024;
        int r = flat >> 7, cc = flat & 127;
        bv[i] = *reinterpret_cast<const float4*>(B + (size_t)r * N + col0 + cc);
    }
    #pragma unroll
    for (int i = 0; i < 8; i++) {
        int flat = tid * 4 + i * 1024;
        int r = flat >> 5, cc = flat & 31;
        As[r * AP + cc + 0] = f2tf32(av[i].x);
        As[r * AP + cc + 1] = f2tf32(av[i].y);
        As[r * AP + cc + 2] = f2tf32(av[i].z);
        As[r * AP + cc + 3] = f2tf32(av[i].w);
    }
    #pragma unroll
    for (int i = 0; i < 4; i++) {
        int flat = tid * 4 + i * 1024;
        int r = flat >> 7, cc = flat & 127;
        Bs[r * BP + cc + 0] = f2tf32(bv[i].x);
        Bs[r * BP + cc + 1] = f2tf32(bv[i].y);
        Bs[r * BP + cc + 2] = f2tf32(bv[i].z);
        Bs[r * BP + cc + 3] = f2tf32(bv[i].w);
    }
    __syncthreads();

    for (int ch = 0; ch < nchunks; ch++) {
        // prefetch next chunk into registers (overlaps with mma below)
        if (ch + 1 < nchunks) {
            int k0 = (ch + 1) * 32;
            #pragma unroll
            for (int i = 0; i < 8; i++) {
                int flat = tid * 4 + i * 1024;
                int r = flat >> 5, cc = flat & 31;
                av[i] = *reinterpret_cast<const float4*>(
                    A + (size_t)(row0 + r) * K + k0 + cc);
            }
            #pragma unroll
            for (int i = 0; i < 4; i++) {
                int flat = tid * 4 + i * 1024;
                int r = flat >> 7, cc = flat & 127;
                bv[i] = *reinterpret_cast<const float4*>(
                    B + (size_t)(k0 + r) * N + col0 + cc);
            }
        }

        #pragma unroll
        for (int ks = 0; ks < 4; ks++) {
            uint32_t a[4][4], b[8][2];
            #pragma unroll
            for (int mt = 0; mt < 4; mt++) {
                int base = (wm * 64 + mt * 16) * AP + ks * 8;
                a[mt][0] = As[base + g * AP + tg];
                a[mt][1] = As[base + (g + 8) * AP + tg];
                a[mt][2] = As[base + g * AP + tg + 4];
                a[mt][3] = As[base + (g + 8) * AP + tg + 4];
            }
            #pragma unroll
            for (int nt = 0; nt < 8; nt++) {
                int bb = (ks * 8 + tg) * BP + wn * 64 + nt * 8 + g;
                b[nt][0] = Bs[bb];
                b[nt][1] = Bs[bb + 4 * BP];
            }
            #pragma unroll
            for (int mt = 0; mt < 4; mt++)
                #pragma unroll
                for (int nt = 0; nt < 8; nt++)
                    mma_tf32(c[mt][nt], a[mt], b[nt][0], b[nt][1]);
        }

        if (ch + 1 < nchunks) {
            __syncthreads();   // all warps done reading chunk ch
            #pragma unroll
            for (int i = 0; i < 8; i++) {
                int flat = tid * 4 + i * 1024;
                int r = flat >> 5, cc = flat & 31;
                As[r * AP + cc + 0] = f2tf32(av[i].x);
                As[r * AP + cc + 1] = f2tf32(av[i].y);
                As[r * AP + cc + 2] = f2tf32(av[i].z);
                As[r * AP + cc + 3] = f2tf32(av[i].w);
            }
            #pragma unroll
            for (int i = 0; i < 4; i++) {
                int flat = tid * 4 + i * 1024;
                int r = flat >> 7, cc = flat & 127;
                Bs[r * BP + cc + 0] = f2tf32(bv[i].x);
                Bs[r * BP + cc + 1] = f2tf32(bv[i].y);
                Bs[r * BP + cc + 2] = f2tf32(bv[i].z);
                Bs[r * BP + cc + 3] = f2tf32(bv[i].w);
            }
            __syncthreads();
        }
    }

    #pragma unroll
    for (int mt = 0; mt < 4; mt++) {
        int r = row0 + wm * 64 + mt * 16 + g;
        #pragma unroll
        for (int nt = 0; nt < 8; nt++) {
            int cc = col0 + wn * 64 + nt * 8 + 2 * tg;
            float bx = 0.f, by = 0.f;
            if (bias) { bx = bias[cc]; by = bias[cc + 1]; }
            float2 v0 = make_float2(c[mt][nt][0] + bx, c[mt][nt][1] + by);
            float2 v1 = make_float2(c[mt][nt][2] + bx, c[mt][nt][3] + by);
            *reinterpret_cast<float2*>(C + (size_t)r * N + cc) = v0;
            *reinterpret_cast<float2*>(C + (size_t)(r + 8) * N + cc) = v1;
        }
    }
}

// ---------------------------------------------------------------------------
// Flash attention. 256 thr / 8 warps. CTA: 256 q-rows of one (batch, head).
// Warp owns 32 q-rows = 2 mtiles processed sequentially (S/softmax/P/PV per
// mtile) so K/V B-fragments are shared across both mtiles. kv tiles of 128.
// ---------------------------------------------------------------------------
#define QP 68
#define PP 132
#define FA_KS    (256 * QP)
#define FA_VS    (FA_KS + 128 * QP)
#define FA_PS    (FA_VS + 128 * QP)
#define FA_WORDS (FA_PS + 128 * PP)
#define FA_BYTES (FA_WORDS * 4)          // 206848 B

__global__ __launch_bounds__(256, 1) void mma_flash_kernel(
    const float* __restrict__ qkv, float* __restrict__ attn)
{
    extern __shared__ uint32_t sm[];
    uint32_t* Qs = sm;             // 256 x QP
    uint32_t* Ks = sm + FA_KS;     // 128 x QP
    uint32_t* Vs = sm + FA_VS;     // 128 x QP
    uint32_t* Ps = sm + FA_PS;     // 128 x PP (per-warp 16 rows, reused per mt)

    const int tid = threadIdx.x;
    const int wid = tid >> 5, lane = tid & 31;
    const int g = lane >> 2, tg = lane & 3;
    const int qt = blockIdx.x, h = blockIdx.y, bb = blockIdx.z;
    const int tok_q0 = bb * TSEQ + qt * 256;

    // Q tile 256x64 (pre-scaled by dh^-0.5 = 0.125)
    #pragma unroll
    for (int i = 0; i < 16; i++) {
        int flat = tid * 4 + i * 1024;
        int r = flat >> 6, cc = flat & 63;
        float4 v = *reinterpret_cast<const float4*>(
            qkv + (size_t)(tok_q0 + r) * QKVN + h * DH + cc);
        Qs[r * QP + cc + 0] = f2tf32(v.x * 0.125f);
        Qs[r * QP + cc + 1] = f2tf32(v.y * 0.125f);
        Qs[r * QP + cc + 2] = f2tf32(v.z * 0.125f);
        Qs[r * QP + cc + 3] = f2tf32(v.w * 0.125f);
    }

    float m[2][2], l[2][2];
    #pragma unroll
    for (int mt = 0; mt < 2; mt++) {
        m[mt][0] = -1e30f; m[mt][1] = -1e30f;
        l[mt][0] = 0.f;    l[mt][1] = 0.f;
    }
    float o[2][8][4];
    #pragma unroll
    for (int mt = 0; mt < 2; mt++)
        #pragma unroll
        for (int nt = 0; nt < 8; nt++)
            #pragma unroll
            for (int j = 0; j < 4; j++) o[mt][nt][j] = 0.f;

    for (int kt = 0; kt < TSEQ / 128; kt++) {
        const int tok_k0 = bb * TSEQ + kt * 128;
        __syncthreads();   // prior iter done reading Ks/Vs
        #pragma unroll
        for (int i = 0; i < 8; i++) {
            int flat = tid * 4 + i * 1024;
            int r = flat >> 6, cc = flat & 63;
            size_t base = (size_t)(tok_k0 + r) * QKVN + h * DH + cc;
            float4 kv4 = *reinterpret_cast<const float4*>(qkv + base + INNER);
            float4 vv4 = *reinterpret_cast<const float4*>(qkv + base + 2 * INNER);
            Ks[r * QP + cc + 0] = f2tf32(kv4.x);
            Ks[r * QP + cc + 1] = f2tf32(kv4.y);
            Ks[r * QP + cc + 2] = f2tf32(kv4.z);
            Ks[r * QP + cc + 3] = f2tf32(kv4.w);
            Vs[r * QP + cc + 0] = f2tf32(vv4.x);
            Vs[r * QP + cc + 1] = f2tf32(vv4.y);
            Vs[r * QP + cc + 2] = f2tf32(vv4.z);
            Vs[r * QP + cc + 3] = f2tf32(vv4.w);
        }
        __syncthreads();

        #pragma unroll
        for (int mt = 0; mt < 2; mt++) {
            const int wb = wid * 32 + mt * 16;   // q-row base for this mtile

            // ---- S = Q @ K^T : 16 x 128 (16 ntiles), K = 64 (8 ks)
            float s[16][4];
            #pragma unroll
            for (int nt = 0; nt < 16; nt++)
                #pragma unroll
                for (int j = 0; j < 4; j++) s[nt][j] = 0.f;
            #pragma unroll
            for (int ks = 0; ks < 8; ks++) {
                uint32_t a[4];
                int base = wb * QP + ks * 8;
                a[0] = Qs[base + g * QP + tg];
                a[1] = Qs[base + (g + 8) * QP + tg];
                a[2] = Qs[base + g * QP + tg + 4];
                a[3] = Qs[base + (g + 8) * QP + tg + 4];
                #pragma unroll
                for (int nt = 0; nt < 16; nt++) {
                    int bidx = (nt * 8 + g) * QP + ks * 8 + tg;
                    mma_tf32(s[nt], a, Ks[bidx], Ks[bidx + 4]);
                }
            }

            // ---- online softmax (rows wb+g and wb+g+8)
            float mx0 = -1e30f, mx1 = -1e30f;
            #pragma unroll
            for (int nt = 0; nt < 16; nt++) {
                mx0 = fmaxf(mx0, fmaxf(s[nt][0], s[nt][1]));
                mx1 = fmaxf(mx1, fmaxf(s[nt][2], s[nt][3]));
            }
            mx0 = fmaxf(mx0, __shfl_xor_sync(0xffffffffu, mx0, 1));
            mx0 = fmaxf(mx0, __shfl_xor_sync(0xffffffffu, mx0, 2));
            mx1 = fmaxf(mx1, __shfl_xor_sync(0xffffffffu, mx1, 1));
            mx1 = fmaxf(mx1, __shfl_xor_sync(0xffffffffu, mx1, 2));
            const float mn0 = fmaxf(m[mt][0], mx0);
            const float mn1 = fmaxf(m[mt][1], mx1);
            const float al0 = __expf(m[mt][0] - mn0);
            const float al1 = __expf(m[mt][1] - mn1);
            float sum0 = 0.f, sum1 = 0.f;
            #pragma unroll
            for (int nt = 0; nt < 16; nt++) {
                s[nt][0] = __expf(s[nt][0] - mn0);
                s[nt][1] = __expf(s[nt][1] - mn0);
                s[nt][2] = __expf(s[nt][2] - mn1);
                s[nt][3] = __expf(s[nt][3] - mn1);
                sum0 += s[nt][0] + s[nt][1];
                sum1 += s[nt][2] + s[nt][3];
            }
            sum0 += __shfl_xor_sync(0xffffffffu, sum0, 1);
            sum0 += __shfl_xor_sync(0xffffffffu, sum0, 2);
            sum1 += __shfl_xor_sync(0xffffffffu, sum1, 1);
            sum1 += __shfl_xor_sync(0xffffffffu, sum1, 2);
            l[mt][0] = l[mt][0] * al0 + sum0; m[mt][0] = mn0;
            l[mt][1] = l[mt][1] * al1 + sum1; m[mt][1] = mn1;
            #pragma unroll
            for (int nt = 0; nt < 8; nt++) {
                o[mt][nt][0] *= al0; o[mt][nt][1] *= al0;
                o[mt][nt][2] *= al1; o[mt][nt][3] *= al1;
            }

            // ---- P -> SMEM (warp-private 16 rows, WAR vs prior PV reads)
            __syncwarp();
            {
                int r0 = (wid * 16 + g) * PP, r1 = (wid * 16 + g + 8) * PP;
                #pragma unroll
                for (int nt = 0; nt < 16; nt++) {
                    int cc = nt * 8 + 2 * tg;
                    Ps[r0 + cc]     = f2tf32(s[nt][0]);
                    Ps[r0 + cc + 1] = f2tf32(s[nt][1]);
                    Ps[r1 + cc]     = f2tf32(s[nt][2]);
                    Ps[r1 + cc + 1] = f2tf32(s[nt][3]);
                }
            }
            __syncwarp();

            // ---- O += P @ V : 16 x 64 (8 ntiles), K = 128 (16 ks)
            #pragma unroll
            for (int ks = 0; ks < 16; ks++) {
                uint32_t a[4];
                int base = (wid * 16) * PP + ks * 8;
                a[0] = Ps[base + g * PP + tg];
                a[1] = Ps[base + (g + 8) * PP + tg];
                a[2] = Ps[base + g * PP + tg + 4];
                a[3] = Ps[base + (g + 8) * PP + tg + 4];
                #pragma unroll
                for (int nt = 0; nt < 8; nt++) {
                    int bidx = (ks * 8 + tg) * QP + nt * 8 + g;
                    mma_tf32(o[mt][nt], a, Vs[bidx], Vs[bidx + 4 * QP]);
                }
            }
        }
    }

    #pragma unroll
    for (int mt = 0; mt < 2; mt++) {
        const float li0 = 1.f / l[mt][0], li1 = 1.f / l[mt][1];
        const int r = tok_q0 + wid * 32 + mt * 16 + g;
        #pragma unroll
        for (int nt = 0; nt < 8; nt++) {
            int cc = h * DH + nt * 8 + 2 * tg;
            float2 v0 = make_float2(o[mt][nt][0] * li0, o[mt][nt][1] * li0);
            float2 v1 = make_float2(o[mt][nt][2] * li1, o[mt][nt][3] * li1);
            *reinterpret_cast<float2*>(attn + (size_t)r * INNER + cc) = v0;
            *reinterpret_cast<float2*>(attn + (size_t)(r + 8) * INNER + cc) = v1;
        }
    }
}

// ---------------------------------------------------------------------------
extern "C" void kernel_launch(void* const* d_in, const int* in_sizes, int n_in,
                              void* d_out, int out_size)
{
    (void)in_sizes; (void)n_in; (void)out_size;
    const float* x     = (const float*)d_in[0];
    const float* w_qkv = (const float*)d_in[1];
    const float* w_out = (const float*)d_in[2];
    const float* b_out = (const float*)d_in[3];
    float* out = (float*)d_out;

    float *qkv_p, *attn_p;
    cudaGetSymbolAddress((void**)&qkv_p,  g_qkv);
    cudaGetSymbolAddress((void**)&attn_p, g_attn);

    cudaFuncSetAttribute(mma_gemm_kernel,
        cudaFuncAttributeMaxDynamicSharedMemorySize, GM_BYTES);
    cudaFuncSetAttribute(mma_flash_kernel,
        cudaFuncAttributeMaxDynamicSharedMemorySize, FA_BYTES);

    // QKV projection: [16384,512] @ [512,768]
    mma_gemm_kernel<<<dim3(QKVN / 128, NTOK / 256), 256, GM_BYTES>>>(
        x, w_qkv, nullptr, qkv_p, NTOK, QKVN, DMODEL);
    // attention: 256 q-rows per CTA
    mma_flash_kernel<<<dim3(TSEQ / 256, HEADS, 8), 256, FA_BYTES>>>(
        qkv_p, attn_p);
    // output projection: [16384,256] @ [256,512] + bias
    mma_gemm_kernel<<<dim3(DMODEL / 128, NTOK / 256), 256, GM_BYTES>>>(
        attn_p, w_out, b_out, out, NTOK, DMODEL, INNER);
}

// round 6
// speedup vs baseline: 3.6169x; 1.2021x over previous
#include <cuda_runtime.h>
#include <cstdint>

// ===========================================================================
// SelfAttention via mma.sync tf32 — Round 6: flash restructured to kv-tile 64
// so BOTH K and V b-fragments are shared across the warp's two mtiles
// (B-frag LDS nearly halved), all fragment pitches bank-conflict-free.
// GEMM keeps BP=136 conflict fix from round 5.
//   K1: mma_gemm   x @ w_qkv            -> g_qkv  [16384 x 768]
//   K2: mma_flash  attention            -> g_attn [16384 x 256]
//   K1: mma_gemm   g_attn @ w_out + b   -> out    [16384 x 512]
// ===========================================================================

#define NTOK   16384
#define DMODEL 512
#define INNER  256
#define QKVN   768
#define HEADS  4
#define DH     64
#define TSEQ   2048

__device__ float g_qkv[NTOK * QKVN];    // 48 MB
__device__ float g_attn[NTOK * INNER];  // 16 MB

__device__ __forceinline__ uint32_t f2tf32(float x) {
    uint32_t r;
    asm("cvt.rna.tf32.f32 %0, %1;" : "=r"(r) : "f"(x));
    return r;
}

// D = A(16x8) @ B(8x8) + D, tf32 inputs, f32 accum
__device__ __forceinline__ void mma_tf32(float* c, const uint32_t* a,
                                         uint32_t b0, uint32_t b1) {
    asm volatile(
        "mma.sync.aligned.m16n8k8.row.col.f32.tf32.tf32.f32 "
        "{%0,%1,%2,%3}, {%4,%5,%6,%7}, {%8,%9}, {%0,%1,%2,%3};"
        : "+f"(c[0]), "+f"(c[1]), "+f"(c[2]), "+f"(c[3])
        : "r"(a[0]), "r"(a[1]), "r"(a[2]), "r"(a[3]), "r"(b0), "r"(b1));
}

// ---------------------------------------------------------------------------
// GEMM: C[M,N] = A[M,K] @ B[K,N] (+bias). 256 thr, CTA tile 256x128,
// kchunk 32, warp grid 4(m) x 2(n), warp tile 64x64 (4 mtiles x 8 ntiles).
// AP=36 (==4 mod 32: A-frag banks 4g+tg). BP=136 (==8: B-frag banks 8tg+g).
// ---------------------------------------------------------------------------
#define AP 36
#define BP 136
#define GM_BS    (256 * AP)
#define GM_WORDS (GM_BS + 32 * BP)
#define GM_BYTES (GM_WORDS * 4)          // 54272 B

__global__ __launch_bounds__(256, 1) void mma_gemm_kernel(
    const float* __restrict__ A, const float* __restrict__ B,
    const float* __restrict__ bias, float* __restrict__ C,
    int M, int N, int K)
{
    extern __shared__ uint32_t sm[];
    uint32_t* As = sm;            // 256 x AP
    uint32_t* Bs = sm + GM_BS;    // 32 x BP

    const int tid = threadIdx.x;
    const int wid = tid >> 5, lane = tid & 31;
    const int g = lane >> 2, tg = lane & 3;
    const int wm = wid & 3, wn = wid >> 2;
    const int row0 = blockIdx.y * 256, col0 = blockIdx.x * 128;

    float c[4][8][4];
    #pragma unroll
    for (int mt = 0; mt < 4; mt++)
        #pragma unroll
        for (int nt = 0; nt < 8; nt++)
            #pragma unroll
            for (int j = 0; j < 4; j++) c[mt][nt][j] = 0.f;

    const int nchunks = K >> 5;
    float4 av[8], bv[4];

    #pragma unroll
    for (int i = 0; i < 8; i++) {
        int flat = tid * 4 + i * 1024;
        int r = flat >> 5, cc = flat & 31;
        av[i] = *reinterpret_cast<const float4*>(A + (size_t)(row0 + r) * K + cc);
    }
    #pragma unroll
    for (int i = 0; i < 4; i++) {
        int flat = tid * 4 + i * 1024;
        int r = flat >> 7, cc = flat & 127;
        bv[i] = *reinterpret_cast<const float4*>(B + (size_t)r * N + col0 + cc);
    }
    #pragma unroll
    for (int i = 0; i < 8; i++) {
        int flat = tid * 4 + i * 1024;
        int r = flat >> 5, cc = flat & 31;
        As[r * AP + cc + 0] = f2tf32(av[i].x);
        As[r * AP + cc + 1] = f2tf32(av[i].y);
        As[r * AP + cc + 2] = f2tf32(av[i].z);
        As[r * AP + cc + 3] = f2tf32(av[i].w);
    }
    #pragma unroll
    for (int i = 0; i < 4; i++) {
        int flat = tid * 4 + i * 1024;
        int r = flat >> 7, cc = flat & 127;
        Bs[r * BP + cc + 0] = f2tf32(bv[i].x);
        Bs[r * BP + cc + 1] = f2tf32(bv[i].y);
        Bs[r * BP + cc + 2] = f2tf32(bv[i].z);
        Bs[r * BP + cc + 3] = f2tf32(bv[i].w);
    }
    __syncthreads();

    for (int ch = 0; ch < nchunks; ch++) {
        if (ch + 1 < nchunks) {
            int k0 = (ch + 1) * 32;
            #pragma unroll
            for (int i = 0; i < 8; i++) {
                int flat = tid * 4 + i * 1024;
                int r = flat >> 5, cc = flat & 31;
                av[i] = *reinterpret_cast<const float4*>(
                    A + (size_t)(row0 + r) * K + k0 + cc);
            }
            #pragma unroll
            for (int i = 0; i < 4; i++) {
                int flat = tid * 4 + i * 1024;
                int r = flat >> 7, cc = flat & 127;
                bv[i] = *reinterpret_cast<const float4*>(
                    B + (size_t)(k0 + r) * N + col0 + cc);
            }
        }

        #pragma unroll
        for (int ks = 0; ks < 4; ks++) {
            uint32_t a[4][4], b[8][2];
            #pragma unroll
            for (int mt = 0; mt < 4; mt++) {
                int base = (wm * 64 + mt * 16) * AP + ks * 8;
                a[mt][0] = As[base + g * AP + tg];
                a[mt][1] = As[base + (g + 8) * AP + tg];
                a[mt][2] = As[base + g * AP + tg + 4];
                a[mt][3] = As[base + (g + 8) * AP + tg + 4];
            }
            #pragma unroll
            for (int nt = 0; nt < 8; nt++) {
                int bb = (ks * 8 + tg) * BP + wn * 64 + nt * 8 + g;
                b[nt][0] = Bs[bb];
                b[nt][1] = Bs[bb + 4 * BP];
            }
            #pragma unroll
            for (int mt = 0; mt < 4; mt++)
                #pragma unroll
                for (int nt = 0; nt < 8; nt++)
                    mma_tf32(c[mt][nt], a[mt], b[nt][0], b[nt][1]);
        }

        if (ch + 1 < nchunks) {
            __syncthreads();
            #pragma unroll
            for (int i = 0; i < 8; i++) {
                int flat = tid * 4 + i * 1024;
                int r = flat >> 5, cc = flat & 31;
                As[r * AP + cc + 0] = f2tf32(av[i].x);
                As[r * AP + cc + 1] = f2tf32(av[i].y);
                As[r * AP + cc + 2] = f2tf32(av[i].z);
                As[r * AP + cc + 3] = f2tf32(av[i].w);
            }
            #pragma unroll
            for (int i = 0; i < 4; i++) {
                int flat = tid * 4 + i * 1024;
                int r = flat >> 7, cc = flat & 127;
                Bs[r * BP + cc + 0] = f2tf32(bv[i].x);
                Bs[r * BP + cc + 1] = f2tf32(bv[i].y);
                Bs[r * BP + cc + 2] = f2tf32(bv[i].z);
                Bs[r * BP + cc + 3] = f2tf32(bv[i].w);
            }
            __syncthreads();
        }
    }

    #pragma unroll
    for (int mt = 0; mt < 4; mt++) {
        int r = row0 + wm * 64 + mt * 16 + g;
        #pragma unroll
        for (int nt = 0; nt < 8; nt++) {
            int cc = col0 + wn * 64 + nt * 8 + 2 * tg;
            float bx = 0.f, by = 0.f;
            if (bias) { bx = bias[cc]; by = bias[cc + 1]; }
            float2 v0 = make_float2(c[mt][nt][0] + bx, c[mt][nt][1] + by);
            float2 v1 = make_float2(c[mt][nt][2] + bx, c[mt][nt][3] + by);
            *reinterpret_cast<float2*>(C + (size_t)r * N + cc) = v0;
            *reinterpret_cast<float2*>(C + (size_t)(r + 8) * N + cc) = v1;
        }
    }
}

// ---------------------------------------------------------------------------
// Flash attention. 256 thr / 8 warps. CTA: 256 q-rows of one (batch, head).
// Warp owns 32 q-rows = 2 mtiles, kv tiles of 64. Both mtiles' S computed in
// one ks loop (shared K b-frags); one PV pass (shared V b-frags).
// Pitches: Qs/Ks/Ps 68 (==4 mod 32), Vs 72 (==8 mod 32). All frag LDS clean.
// smem = 256*68 + 64*68 + 64*72 + 256*68 words = 175104 B.
// ---------------------------------------------------------------------------
#define QP 68
#define VP 72
#define PP 68
#define FA_KS    (256 * QP)
#define FA_VS    (FA_KS + 64 * QP)
#define FA_PS    (FA_VS + 64 * VP)
#define FA_WORDS (FA_PS + 256 * PP)
#define FA_BYTES (FA_WORDS * 4)          // 175104 B

__global__ __launch_bounds__(256, 1) void mma_flash_kernel(
    const float* __restrict__ qkv, float* __restrict__ attn)
{
    extern __shared__ uint32_t sm[];
    uint32_t* Qs = sm;             // 256 x QP
    uint32_t* Ks = sm + FA_KS;     // 64 x QP
    uint32_t* Vs = sm + FA_VS;     // 64 x VP
    uint32_t* Ps = sm + FA_PS;     // 256 x PP (warp w owns rows [32w,32w+32))

    const int tid = threadIdx.x;
    const int wid = tid >> 5, lane = tid & 31;
    const int g = lane >> 2, tg = lane & 3;
    const int qt = blockIdx.x, h = blockIdx.y, bb = blockIdx.z;
    const int tok_q0 = bb * TSEQ + qt * 256;
    const int wb0 = wid * 32, wb1 = wid * 32 + 16;

    // Q tile 256x64 (pre-scaled by dh^-0.5 = 0.125)
    #pragma unroll
    for (int i = 0; i < 16; i++) {
        int flat = tid * 4 + i * 1024;
        int r = flat >> 6, cc = flat & 63;
        float4 v = *reinterpret_cast<const float4*>(
            qkv + (size_t)(tok_q0 + r) * QKVN + h * DH + cc);
        Qs[r * QP + cc + 0] = f2tf32(v.x * 0.125f);
        Qs[r * QP + cc + 1] = f2tf32(v.y * 0.125f);
        Qs[r * QP + cc + 2] = f2tf32(v.z * 0.125f);
        Qs[r * QP + cc + 3] = f2tf32(v.w * 0.125f);
    }

    float m[2][2], l[2][2];
    #pragma unroll
    for (int mt = 0; mt < 2; mt++) {
        m[mt][0] = -1e30f; m[mt][1] = -1e30f;
        l[mt][0] = 0.f;    l[mt][1] = 0.f;
    }
    float o[2][8][4];
    #pragma unroll
    for (int mt = 0; mt < 2; mt++)
        #pragma unroll
        for (int nt = 0; nt < 8; nt++)
            #pragma unroll
            for (int j = 0; j < 4; j++) o[mt][nt][j] = 0.f;

    for (int kt = 0; kt < TSEQ / 64; kt++) {
        const int tok_k0 = bb * TSEQ + kt * 64;
        __syncthreads();   // prior iter done reading Ks/Vs (and Q stores, kt=0)
        #pragma unroll
        for (int i = 0; i < 4; i++) {     // K/V tiles 64x64 each
            int flat = tid * 4 + i * 1024;
            int r = flat >> 6, cc = flat & 63;
            size_t base = (size_t)(tok_k0 + r) * QKVN + h * DH + cc;
            float4 kv4 = *reinterpret_cast<const float4*>(qkv + base + INNER);
            float4 vv4 = *reinterpret_cast<const float4*>(qkv + base + 2 * INNER);
            Ks[r * QP + cc + 0] = f2tf32(kv4.x);
            Ks[r * QP + cc + 1] = f2tf32(kv4.y);
            Ks[r * QP + cc + 2] = f2tf32(kv4.z);
            Ks[r * QP + cc + 3] = f2tf32(kv4.w);
            Vs[r * VP + cc + 0] = f2tf32(vv4.x);
            Vs[r * VP + cc + 1] = f2tf32(vv4.y);
            Vs[r * VP + cc + 2] = f2tf32(vv4.z);
            Vs[r * VP + cc + 3] = f2tf32(vv4.w);
        }
        __syncthreads();

        // ---- S = Q @ K^T : both mtiles, shared K b-frags. 8 ntiles, 8 ks.
        float s0[8][4], s1[8][4];
        #pragma unroll
        for (int nt = 0; nt < 8; nt++)
            #pragma unroll
            for (int j = 0; j < 4; j++) { s0[nt][j] = 0.f; s1[nt][j] = 0.f; }
        #pragma unroll
        for (int ks = 0; ks < 8; ks++) {
            uint32_t a0[4], a1[4];
            int b0a = wb0 * QP + ks * 8, b1a = wb1 * QP + ks * 8;
            a0[0] = Qs[b0a + g * QP + tg];
            a0[1] = Qs[b0a + (g + 8) * QP + tg];
            a0[2] = Qs[b0a + g * QP + tg + 4];
            a0[3] = Qs[b0a + (g + 8) * QP + tg + 4];
            a1[0] = Qs[b1a + g * QP + tg];
            a1[1] = Qs[b1a + (g + 8) * QP + tg];
            a1[2] = Qs[b1a + g * QP + tg + 4];
            a1[3] = Qs[b1a + (g + 8) * QP + tg + 4];
            #pragma unroll
            for (int nt = 0; nt < 8; nt++) {
                int bidx = (nt * 8 + g) * QP + ks * 8 + tg;
                uint32_t kb0 = Ks[bidx], kb1 = Ks[bidx + 4];
                mma_tf32(s0[nt], a0, kb0, kb1);
                mma_tf32(s1[nt], a1, kb0, kb1);
            }
        }

        // ---- online softmax per mtile
        #pragma unroll
        for (int mt = 0; mt < 2; mt++) {
            float (*s)[4] = mt ? s1 : s0;
            float mx0 = -1e30f, mx1 = -1e30f;
            #pragma unroll
            for (int nt = 0; nt < 8; nt++) {
                mx0 = fmaxf(mx0, fmaxf(s[nt][0], s[nt][1]));
                mx1 = fmaxf(mx1, fmaxf(s[nt][2], s[nt][3]));
            }
            mx0 = fmaxf(mx0, __shfl_xor_sync(0xffffffffu, mx0, 1));
            mx0 = fmaxf(mx0, __shfl_xor_sync(0xffffffffu, mx0, 2));
            mx1 = fmaxf(mx1, __shfl_xor_sync(0xffffffffu, mx1, 1));
            mx1 = fmaxf(mx1, __shfl_xor_sync(0xffffffffu, mx1, 2));
            const float mn0 = fmaxf(m[mt][0], mx0);
            const float mn1 = fmaxf(m[mt][1], mx1);
            const float al0 = __expf(m[mt][0] - mn0);
            const float al1 = __expf(m[mt][1] - mn1);
            float sum0 = 0.f, sum1 = 0.f;
            #pragma unroll
            for (int nt = 0; nt < 8; nt++) {
                s[nt][0] = __expf(s[nt][0] - mn0);
                s[nt][1] = __expf(s[nt][1] - mn0);
                s[nt][2] = __expf(s[nt][2] - mn1);
                s[nt][3] = __expf(s[nt][3] - mn1);
                sum0 += s[nt][0] + s[nt][1];
                sum1 += s[nt][2] + s[nt][3];
            }
            sum0 += __shfl_xor_sync(0xffffffffu, sum0, 1);
            sum0 += __shfl_xor_sync(0xffffffffu, sum0, 2);
            sum1 += __shfl_xor_sync(0xffffffffu, sum1, 1);
            sum1 += __shfl_xor_sync(0xffffffffu, sum1, 2);
            l[mt][0] = l[mt][0] * al0 + sum0; m[mt][0] = mn0;
            l[mt][1] = l[mt][1] * al1 + sum1; m[mt][1] = mn1;
            #pragma unroll
            for (int nt = 0; nt < 8; nt++) {
                o[mt][nt][0] *= al0; o[mt][nt][1] *= al0;
                o[mt][nt][2] *= al1; o[mt][nt][3] *= al1;
            }
            // P -> SMEM (warp-private rows)
            const int wb = mt ? wb1 : wb0;
            int r0 = (wb + g) * PP, r1 = (wb + g + 8) * PP;
            #pragma unroll
            for (int nt = 0; nt < 8; nt++) {
                int cc = nt * 8 + 2 * tg;
                Ps[r0 + cc]     = f2tf32(s[nt][0]);
                Ps[r0 + cc + 1] = f2tf32(s[nt][1]);
                Ps[r1 + cc]     = f2tf32(s[nt][2]);
                Ps[r1 + cc + 1] = f2tf32(s[nt][3]);
            }
        }
        __syncwarp();

        // ---- O += P @ V : shared V b-frags across both mtiles. 8 ks.
        #pragma unroll
        for (int ks = 0; ks < 8; ks++) {
            uint32_t a0[4], a1[4];
            int b0a = wb0 * PP + ks * 8, b1a = wb1 * PP + ks * 8;
            a0[0] = Ps[b0a + g * PP + tg];
            a0[1] = Ps[b0a + (g + 8) * PP + tg];
            a0[2] = Ps[b0a + g * PP + tg + 4];
            a0[3] = Ps[b0a + (g + 8) * PP + tg + 4];
            a1[0] = Ps[b1a + g * PP + tg];
            a1[1] = Ps[b1a + (g + 8) * PP + tg];
            a1[2] = Ps[b1a + g * PP + tg + 4];
            a1[3] = Ps[b1a + (g + 8) * PP + tg + 4];
            #pragma unroll
            for (int nt = 0; nt < 8; nt++) {
                int bidx = (ks * 8 + tg) * VP + nt * 8 + g;
                uint32_t vb0 = Vs[bidx], vb1 = Vs[bidx + 4 * VP];
                mma_tf32(o[0][nt], a0, vb0, vb1);
                mma_tf32(o[1][nt], a1, vb0, vb1);
            }
        }
        __syncwarp();   // PV reads of Ps done before next-iter P stores
    }

    #pragma unroll
    for (int mt = 0; mt < 2; mt++) {
        const float li0 = 1.f / l[mt][0], li1 = 1.f / l[mt][1];
        const int r = tok_q0 + wid * 32 + mt * 16 + g;
        #pragma unroll
        for (int nt = 0; nt < 8; nt++) {
            int cc = h * DH + nt * 8 + 2 * tg;
            float2 v0 = make_float2(o[mt][nt][0] * li0, o[mt][nt][1] * li0);
            float2 v1 = make_float2(o[mt][nt][2] * li1, o[mt][nt][3] * li1);
            *reinterpret_cast<float2*>(attn + (size_t)r * INNER + cc) = v0;
            *reinterpret_cast<float2*>(attn + (size_t)(r + 8) * INNER + cc) = v1;
        }
    }
}

// ---------------------------------------------------------------------------
extern "C" void kernel_launch(void* const* d_in, const int* in_sizes, int n_in,
                              void* d_out, int out_size)
{
    (void)in_sizes; (void)n_in; (void)out_size;
    const float* x     = (const float*)d_in[0];
    const float* w_qkv = (const float*)d_in[1];
    const float* w_out = (const float*)d_in[2];
    const float* b_out = (const float*)d_in[3];
    float* out = (float*)d_out;

    float *qkv_p, *attn_p;
    cudaGetSymbolAddress((void**)&qkv_p,  g_qkv);
    cudaGetSymbolAddress((void**)&attn_p, g_attn);

    cudaFuncSetAttribute(mma_gemm_kernel,
        cudaFuncAttributeMaxDynamicSharedMemorySize, GM_BYTES);
    cudaFuncSetAttribute(mma_flash_kernel,
        cudaFuncAttributeMaxDynamicSharedMemorySize, FA_BYTES);

    // QKV projection: [16384,512] @ [512,768]
    mma_gemm_kernel<<<dim3(QKVN / 128, NTOK / 256), 256, GM_BYTES>>>(
        x, w_qkv, nullptr, qkv_p, NTOK, QKVN, DMODEL);
    // attention: 256 q-rows per CTA
    mma_flash_kernel<<<dim3(TSEQ / 256, HEADS, 8), 256, FA_BYTES>>>(
        qkv_p, attn_p);
    // output projection: [16384,256] @ [256,512] + bias
    mma_gemm_kernel<<<dim3(DMODEL / 128, NTOK / 256), 256, GM_BYTES>>>(
        attn_p, w_out, b_out, out, NTOK, DMODEL, INNER);
}